// round 9
// baseline (speedup 1.0000x reference)
#include <cuda_runtime.h>
#include <cstdint>

using ull = unsigned long long;

constexpr int S  = 1024;
constexpr int HD = 256;
constexpr int NB = 128;

// Precomputed input projections: XG[b][s][gate*256 + j], gate order z,r,c
__device__ float XG_buf[(size_t)NB * S * 768];

__device__ __forceinline__ void ffma2(ull& d, ull a, ull b) {
    asm("fma.rn.f32x2 %0, %1, %2, %0;" : "+l"(d) : "l"(a), "l"(b));
}
__device__ __forceinline__ float2 unpk(ull a) {
    float2 r; asm("mov.b64 {%0, %1}, %2;" : "=f"(r.x), "=f"(r.y) : "l"(a)); return r;
}
__device__ __forceinline__ uint32_t smem_u32(const void* p) {
    uint32_t a;
    asm("{ .reg .u64 t; cvta.to.shared.u64 t, %1; cvt.u32.u64 %0, t; }" : "=r"(a) : "l"(p));
    return a;
}
__device__ __forceinline__ uint32_t mapa_rank(uint32_t addr, uint32_t rank) {
    uint32_t r; asm("mapa.shared::cluster.u32 %0, %1, %2;" : "=r"(r) : "r"(addr), "r"(rank));
    return r;
}
__device__ __forceinline__ void st_clu_v2(uint32_t addr, float x, float y) {
    asm volatile("st.shared::cluster.v2.f32 [%0], {%1,%2};"
                 :: "r"(addr), "f"(x), "f"(y) : "memory");
}
__device__ __forceinline__ void st_clu_f32(uint32_t addr, float x) {
    asm volatile("st.shared::cluster.f32 [%0], %1;"
                 :: "r"(addr), "f"(x) : "memory");
}
__device__ __forceinline__ void clu_arrive() {
    asm volatile("barrier.cluster.arrive.aligned;" ::: "memory");
}
__device__ __forceinline__ void clu_wait() {
    asm volatile("barrier.cluster.wait.aligned;" ::: "memory");
}
__device__ __forceinline__ float sigm(float x) { return 1.0f / (1.0f + __expf(-x)); }
__device__ __forceinline__ float tanh_f(float x) {
    x = fminf(fmaxf(x, -15.0f), 15.0f);
    float e = __expf(-2.0f * x);
    return __fdividef(1.0f - e, 1.0f + e);
}
// quad rotation swizzle: logical quad q -> physical quad (rotate within 8-quad group)
__device__ __forceinline__ int swq(int q) { return (q & ~7) | ((q + (q >> 3)) & 7); }

// ============================================================================
// Phase 1: XG = x @ Wg^T + bias  (proven R3 version)
// ============================================================================
constexpr int PRE_SMEM_FLOATS = 32768 + 64 * 260;
constexpr size_t PRE_SMEM_BYTES = PRE_SMEM_FLOATS * sizeof(float);

__global__ void __launch_bounds__(256, 1)
xproj_kernel(const float* __restrict__ x,
             const float* __restrict__ Wzx, const float* __restrict__ bz,
             const float* __restrict__ Wrx, const float* __restrict__ br,
             const float* __restrict__ Wcx, const float* __restrict__ bc)
{
    extern __shared__ float smp[];
    float* XS = smp;            // [128][256]
    float* WS = smp + 32768;    // [64][260]

    const int tid = threadIdx.x, w = tid >> 5, lane = tid & 31;
    const int nt = blockIdx.x % 12, mg = blockIdx.x / 12;
    const int gate = nt >> 2, j0 = (nt & 3) * 64;

    const float* Wsrc = (gate == 0 ? Wzx : (gate == 1 ? Wrx : Wcx)) + (size_t)j0 * HD;
    const float* bsrc = (gate == 0 ? bz : (gate == 1 ? br : bc)) + j0;
    const float b0v = bsrc[lane];
    const float b1v = bsrc[lane + 32];

    for (int i = tid; i < 64 * 64; i += 256) {
        int row = i >> 6, q = i & 63;
        *(float4*)(WS + row * 260 + q * 4) = *(const float4*)(Wsrc + row * 256 + q * 4);
    }

    const int r0 = w * 16;
    for (int it = 0; it < 8; ++it) {
        const int m = mg * 8 + it;
        __syncthreads();
        const float* xs = x + (size_t)m * 128 * HD;
#pragma unroll 8
        for (int i = tid; i < 8192; i += 256)
            *(float4*)(XS + i * 4) = *(const float4*)(xs + (size_t)i * 4);
        __syncthreads();

        ull acc[32];
#pragma unroll
        for (int i = 0; i < 32; ++i) acc[i] = 0ull;

#pragma unroll 4
        for (int kq = 0; kq < 64; ++kq) {
            ulonglong2 wv0 = *(const ulonglong2*)(WS + lane * 260 + kq * 4);
            ulonglong2 wv1 = *(const ulonglong2*)(WS + (lane + 32) * 260 + kq * 4);
#pragma unroll
            for (int r = 0; r < 16; ++r) {
                ulonglong2 xv = *(const ulonglong2*)(XS + (r0 + r) * 256 + kq * 4);
                ffma2(acc[r * 2 + 0], xv.x, wv0.x);
                ffma2(acc[r * 2 + 0], xv.y, wv0.y);
                ffma2(acc[r * 2 + 1], xv.x, wv1.x);
                ffma2(acc[r * 2 + 1], xv.y, wv1.y);
            }
        }

        float* op = XG_buf + ((size_t)m * 128 + r0) * 768 + gate * 256 + j0;
#pragma unroll
        for (int r = 0; r < 16; ++r) {
            float2 f0 = unpk(acc[r * 2 + 0]);
            float2 f1 = unpk(acc[r * 2 + 1]);
            op[(size_t)r * 768 + lane]      = f0.x + f0.y + b0v;
            op[(size_t)r * 768 + lane + 32] = f1.x + f1.y + b1v;
        }
    }
}

// ============================================================================
// Phase 2: recurrence. 32 clusters x 4 CTAs, 512 threads.
// Stage A: z,r own-j full-k (W in regs).  rh, z stay CTA-local.
// Stage B: c-partials for ALL 256 j over own 64 k (Wc in SMEM), push to owner.
// bar1 -> tiny finalize (sum partials, tanh, lerp, h' scalar push) -> bar2.
// ============================================================================
constexpr int R_WC = 0;                    // [256][68] c weights, own k-slice
constexpr int R_H  = 17408;                // [4][260] h, quad-swizzled rows
constexpr int R_RH = 18448;                // [4][68]  r*h (own j == own k range)
constexpr int R_Z  = 18720;                // [4][68]  z (own j)
constexpr int R_XG = 18992;                // [2][4][3][68] = 1632
constexpr int R_CP = 20624;                // [2][4src][4b][68] = 2176
constexpr int REC_FLOATS = R_CP + 2176;    // 22800
constexpr size_t REC_SMEM_BYTES = REC_FLOATS * sizeof(float);  // 91200 B

__global__ void __cluster_dims__(4, 1, 1) __launch_bounds__(512, 1)
gru_rec(const float* __restrict__ h0,
        const float* __restrict__ Wzh, const float* __restrict__ Wrh,
        const float* __restrict__ Wch, float* __restrict__ out)
{
    extern __shared__ float sm[];

    const int tid  = threadIdx.x;
    const int wid  = tid >> 5;
    const int lane = tid & 31;
    const int rank = blockIdx.x & 3;
    const int b0   = (blockIdx.x >> 2) << 2;
    const int j0   = rank << 6;

    // stage-A identity: gate (z:warps0-7, r:warps8-15), 8 j per warp
    const int g1 = wid >> 3;
    const int jb = (wid & 7) * 8;
    const int jl = lane >> 3;        // j-lane 0..3 (2 j each)
    const int kl = lane & 7;         // k-lane 0..7 (32 k each)
    // stage-B identity: lane = jlB(8) x klB(4); warp owns 16 global j
    const int klB = lane & 3;
    const int jlB = lane >> 2;
    const int jB  = 16 * wid + 2 * jlB;   // global j (2 consecutive per thread)

    // ---- init SMEM: Wc k-slice [256][68], h0 (swizzled) ----
    for (int i = tid; i < 4096; i += 512) {
        int row = i >> 4, q = i & 15;
        *(float4*)(sm + R_WC + row * 68 + q * 4) =
            *(const float4*)(Wch + (size_t)row * 256 + j0 + q * 4);
    }
    for (int i = tid; i < 256; i += 512) {
        int bb = i >> 6, q = i & 63;
        *(float4*)(sm + R_H + bb * 260 + swq(q) * 4) =
            *(const float4*)(h0 + (size_t)(b0 + bb) * 256 + q * 4);
    }
    // preload XG for t=0 into buffer 0
    if (tid < 192) {
        int pb = tid / 48, rem = tid % 48, pg = rem >> 4, pq = rem & 15;
        float4 v = *(const float4*)(XG_buf + ((size_t)(b0 + pb) * S + 0) * 768
                                    + pg * 256 + j0 + pq * 4);
        *(float4*)(sm + R_XG + pb * 204 + pg * 68 + pq * 4) = v;
    }

    // ---- stage-A weights -> registers (2 j x 32 k per thread) ----
    ull w1[32];
    {
        const float* wsrc = (g1 == 0 ? Wzh : Wrh)
                          + (size_t)(j0 + jb + jl * 2) * 256 + kl * 32;
#pragma unroll
        for (int jt = 0; jt < 2; ++jt)
#pragma unroll
            for (int c = 0; c < 4; ++c) {
                ulonglong2 v0 = *(const ulonglong2*)(wsrc + jt * 256 + c * 8);
                ulonglong2 v1 = *(const ulonglong2*)(wsrc + jt * 256 + c * 8 + 4);
                w1[jt * 16 + c * 4 + 0] = v0.x;
                w1[jt * 16 + c * 4 + 1] = v0.y;
                w1[jt * 16 + c * 4 + 2] = v1.x;
                w1[jt * 16 + c * 4 + 3] = v1.y;
            }
    }
    __syncthreads();
    clu_arrive(); clu_wait();

    const uint32_t base = smem_u32(sm);
    uint32_t rbase[4];
#pragma unroll
    for (int p = 0; p < 4; ++p) rbase[p] = mapa_rank(base, p);

    // stage-B partial push: dst rank = wid>>2, src slot = own rank
    const uint32_t cp_dst = rbase[wid >> 2]
        + (uint32_t)(R_CP + rank * 272 + 16 * (wid & 3) + 2 * jlB) * 4u;

    // XG producer identity
    const int pb = tid / 48, prem = tid % 48, pg = prem >> 4, pq = prem & 15;
    const float* psrc = XG_buf + (size_t)(b0 + pb) * S * 768 + pg * 256 + j0 + pq * 4;

    // finalize identity (tid < 256): b, own-j local index
    const int fb = tid >> 6, fj = tid & 63;
    const int fe = j0 + fj;
    const uint32_t hoff = (uint32_t)(R_H + fb * 260 + swq(fe >> 2) * 4 + (fe & 3)) * 4u;
    float* outfin = out + (size_t)(b0 + fb) * S * 256 + fe;

    for (int t = 0; t < S; ++t) {
        const int par = t & 1;

        // prefetch next step's XG (global -> regs)
        float4 pxv;
        if (tid < 192 && t + 1 < S)
            pxv = *(const float4*)(psrc + (size_t)(t + 1) * 768);

        const float* xgb = sm + R_XG + par * 816;

        // ================= stage A: z / r gates (register W, full k) =========
        ull acc[8];
#pragma unroll
        for (int i = 0; i < 8; ++i) acc[i] = 0ull;
#pragma unroll
        for (int c = 0; c < 4; ++c) {
#pragma unroll
            for (int b = 0; b < 4; ++b) {
                const float* hb = sm + R_H + b * 260;
                const int p0 = (kl << 3) | ((2 * c + kl) & 7);
                const int p1 = (kl << 3) | ((2 * c + 1 + kl) & 7);
                ulonglong2 h0v = *(const ulonglong2*)(hb + p0 * 4);
                ulonglong2 h1v = *(const ulonglong2*)(hb + p1 * 4);
#pragma unroll
                for (int jt = 0; jt < 2; ++jt) {
                    ffma2(acc[b * 2 + jt], h0v.x, w1[jt * 16 + c * 4 + 0]);
                    ffma2(acc[b * 2 + jt], h0v.y, w1[jt * 16 + c * 4 + 1]);
                    ffma2(acc[b * 2 + jt], h1v.x, w1[jt * 16 + c * 4 + 2]);
                    ffma2(acc[b * 2 + jt], h1v.y, w1[jt * 16 + c * 4 + 3]);
                }
            }
        }
        float s[8];
#pragma unroll
        for (int o = 0; o < 8; ++o) {
            float2 f = unpk(acc[o]);
            float v = f.x + f.y;
            v += __shfl_xor_sync(0xffffffffu, v, 1);
            v += __shfl_xor_sync(0xffffffffu, v, 2);
            v += __shfl_xor_sync(0xffffffffu, v, 4);
            s[o] = v;
        }
        if (kl == 0) {
            if (g1 == 0) {
                // z gate -> local SMEM
#pragma unroll
                for (int b = 0; b < 4; ++b) {
                    int jloc = jb + jl * 2;
                    float z0 = sigm(s[b * 2 + 0] + xgb[b * 204 + jloc]);
                    float z1 = sigm(s[b * 2 + 1] + xgb[b * 204 + jloc + 1]);
                    *(float2*)(sm + R_Z + b * 68 + jloc) = make_float2(z0, z1);
                }
            } else {
                // r gate: rh = sigm * hprev -> local SMEM (own j == own k range)
#pragma unroll
                for (int b = 0; b < 4; ++b) {
                    int jloc = jb + jl * 2;
                    int e = j0 + jloc;
                    float hp0 = sm[R_H + b * 260 + swq(e >> 2) * 4 + (e & 3)];
                    float hp1 = sm[R_H + b * 260 + swq((e + 1) >> 2) * 4 + ((e + 1) & 3)];
                    float r0v = sigm(s[b * 2 + 0] + xgb[b * 204 + 68 + jloc]) * hp0;
                    float r1v = sigm(s[b * 2 + 1] + xgb[b * 204 + 68 + jloc + 1]) * hp1;
                    *(float2*)(sm + R_RH + b * 68 + jloc) = make_float2(r0v, r1v);
                }
            }
        }
        __syncthreads();   // rh complete CTA-locally

        // ========== stage B: c-partials, all 256 j over own 64 k ============
        ull cacc[8];
#pragma unroll
        for (int i = 0; i < 8; ++i) cacc[i] = 0ull;
        const float* wcb = sm + R_WC + jB * 68;
        const float* rhb = sm + R_RH;
#pragma unroll
        for (int m = 0; m < 4; ++m) {
            const int kq = (klB + 4 * m) * 4;
            ulonglong2 rv0 = *(const ulonglong2*)(rhb + 0 * 68 + kq);
            ulonglong2 rv1 = *(const ulonglong2*)(rhb + 1 * 68 + kq);
            ulonglong2 rv2 = *(const ulonglong2*)(rhb + 2 * 68 + kq);
            ulonglong2 rv3 = *(const ulonglong2*)(rhb + 3 * 68 + kq);
#pragma unroll
            for (int jt = 0; jt < 2; ++jt) {
                ulonglong2 wv = *(const ulonglong2*)(wcb + jt * 68 + kq);
                ffma2(cacc[jt * 4 + 0], rv0.x, wv.x);
                ffma2(cacc[jt * 4 + 0], rv0.y, wv.y);
                ffma2(cacc[jt * 4 + 1], rv1.x, wv.x);
                ffma2(cacc[jt * 4 + 1], rv1.y, wv.y);
                ffma2(cacc[jt * 4 + 2], rv2.x, wv.x);
                ffma2(cacc[jt * 4 + 2], rv2.y, wv.y);
                ffma2(cacc[jt * 4 + 3], rv3.x, wv.x);
                ffma2(cacc[jt * 4 + 3], rv3.y, wv.y);
            }
        }
        float sb[8];
#pragma unroll
        for (int o = 0; o < 8; ++o) {
            float2 f = unpk(cacc[o]);
            float v = f.x + f.y;
            v += __shfl_xor_sync(0xffffffffu, v, 1);
            v += __shfl_xor_sync(0xffffffffu, v, 2);
            sb[o] = v;
        }
        if (klB == 0) {
            uint32_t dst = cp_dst + (uint32_t)par * 4352u;  // 1088 floats
#pragma unroll
            for (int b = 0; b < 4; ++b)
                st_clu_v2(dst + (uint32_t)b * 272u, sb[b], sb[4 + b]);
        }
        // commit next-step XG while pushes drain
        if (tid < 192 && t + 1 < S)
            *(float4*)(sm + R_XG + (par ^ 1) * 816 + pb * 204 + pg * 68 + pq * 4) = pxv;
        clu_arrive(); clu_wait();   // bar1: all c-partials arrived

        // ================= finalize (tiny) ==================================
        if (tid < 256) {
            const float* cp = sm + R_CP + par * 1088 + fb * 68 + fj;
            float ssum = cp[0] + cp[272] + cp[544] + cp[816];
            float ct = tanh_f(ssum + xgb[fb * 204 + 136 + fj]);
            float zv = sm[R_Z + fb * 68 + fj];
            float hp = __uint_as_float(
                *(const unsigned*)((const char*)sm + hoff));
            float hn = fmaf(zv, ct - hp, hp);
#pragma unroll
            for (int p = 0; p < 4; ++p) st_clu_f32(rbase[p] + hoff, hn);
            outfin[(size_t)t * 256] = hn;
        }
        clu_arrive(); clu_wait();   // bar2: h' visible everywhere
    }
}

extern "C" void kernel_launch(void* const* d_in, const int* in_sizes, int n_in,
                              void* d_out, int out_size) {
    const float* x   = (const float*)d_in[0];
    const float* h0  = (const float*)d_in[1];
    const float* Wzx = (const float*)d_in[2];
    const float* bz  = (const float*)d_in[3];
    const float* Wzh = (const float*)d_in[4];
    const float* Wrx = (const float*)d_in[5];
    const float* br  = (const float*)d_in[6];
    const float* Wrh = (const float*)d_in[7];
    const float* Wcx = (const float*)d_in[8];
    const float* bc  = (const float*)d_in[9];
    const float* Wch = (const float*)d_in[10];
    float* out = (float*)d_out;

    cudaFuncSetAttribute(xproj_kernel, cudaFuncAttributeMaxDynamicSharedMemorySize,
                         (int)PRE_SMEM_BYTES);
    cudaFuncSetAttribute(gru_rec, cudaFuncAttributeMaxDynamicSharedMemorySize,
                         (int)REC_SMEM_BYTES);

    xproj_kernel<<<12 * 128, 256, PRE_SMEM_BYTES>>>(x, Wzx, bz, Wrx, br, Wcx, bc);
    gru_rec<<<128, 512, REC_SMEM_BYTES>>>(h0, Wzh, Wrh, Wch, out);
}

// round 12
// speedup vs baseline: 1.0895x; 1.0895x over previous
#include <cuda_runtime.h>
#include <cstdint>

using ull = unsigned long long;

constexpr int S  = 1024;
constexpr int HD = 256;
constexpr int NB = 128;

// Precomputed input projections: XG[b][s][gate*256 + j], gate order z,r,c
__device__ float XG_buf[(size_t)NB * S * 768];
// bf16 hi/lo split of x (error-compensated GEMM operands)
__device__ unsigned short Xh_buf[(size_t)NB * S * HD];
__device__ unsigned short Xl_buf[(size_t)NB * S * HD];

__device__ __forceinline__ void ffma2(ull& d, ull a, ull b) {
    asm("fma.rn.f32x2 %0, %1, %2, %0;" : "+l"(d) : "l"(a), "l"(b));
}
__device__ __forceinline__ float2 unpk(ull a) {
    float2 r; asm("mov.b64 {%0, %1}, %2;" : "=f"(r.x), "=f"(r.y) : "l"(a)); return r;
}
__device__ __forceinline__ uint32_t smem_u32(const void* p) {
    uint32_t a;
    asm("{ .reg .u64 t; cvta.to.shared.u64 t, %1; cvt.u32.u64 %0, t; }" : "=r"(a) : "l"(p));
    return a;
}
__device__ __forceinline__ uint32_t mapa_rank(uint32_t addr, uint32_t rank) {
    uint32_t r; asm("mapa.shared::cluster.u32 %0, %1, %2;" : "=r"(r) : "r"(addr), "r"(rank));
    return r;
}
__device__ __forceinline__ void st_clu_v4(uint32_t addr, float4 v) {
    asm volatile("st.shared::cluster.v4.f32 [%0], {%1,%2,%3,%4};"
                 :: "r"(addr), "f"(v.x), "f"(v.y), "f"(v.z), "f"(v.w) : "memory");
}
__device__ __forceinline__ void clu_arrive() {
    asm volatile("barrier.cluster.arrive.aligned;" ::: "memory");
}
__device__ __forceinline__ void clu_wait() {
    asm volatile("barrier.cluster.wait.aligned;" ::: "memory");
}
__device__ __forceinline__ float sigm(float x) { return 1.0f / (1.0f + __expf(-x)); }
__device__ __forceinline__ float tanh_f(float x) {
    x = fminf(fmaxf(x, -15.0f), 15.0f);
    float e = __expf(-2.0f * x);
    return __fdividef(1.0f - e, 1.0f + e);
}
__device__ __forceinline__ int swq(int q) { return (q & ~7) | ((q + (q >> 3)) & 7); }

// pack 2 fp32 -> bf16x2: low half = lo, high half = hi
__device__ __forceinline__ uint32_t bf2(float lo, float hi) {
    uint32_t r;
    asm("cvt.rn.bf16x2.f32 %0, %1, %2;" : "=r"(r) : "f"(hi), "f"(lo));
    return r;
}

// ============================================================================
// Phase 0: split x (fp32) into bf16 hi + lo buffers.
// ============================================================================
__global__ void __launch_bounds__(256)
xsplit_kernel(const float* __restrict__ x)
{
    size_t i = (size_t)blockIdx.x * 256 + threadIdx.x;   // one 8-elem group
    const float* p = x + i * 8;
    float4 f0 = *(const float4*)p;
    float4 f1 = *(const float4*)(p + 4);
    float v[8] = {f0.x, f0.y, f0.z, f0.w, f1.x, f1.y, f1.z, f1.w};
    uint32_t h[4], l[4];
#pragma unroll
    for (int q = 0; q < 4; ++q) {
        float a = v[q * 2], b = v[q * 2 + 1];
        uint32_t hp = bf2(a, b);
        float ah = __uint_as_float(hp << 16);
        float bh = __uint_as_float(hp & 0xffff0000u);
        h[q] = hp;
        l[q] = bf2(a - ah, b - bh);
    }
    *(uint4*)(Xh_buf + i * 8) = make_uint4(h[0], h[1], h[2], h[3]);
    *(uint4*)(Xl_buf + i * 8) = make_uint4(l[0], l[1], l[2], l[3]);
}

// ============================================================================
// Phase 1: XG = x @ Wg^T + bias — bf16x3 HMMA (mma m16n8k16, fp32 accum).
// grid = 12 n-tiles * 128 m-groups; CTA tile 128m x 64n; 8 warps of 32x32.
// ============================================================================
constexpr int XH_OFF = 0;                 // bf16 [128][256] swizzled (65536 B)
constexpr int XL_OFF = 65536;
constexpr int WH_OFF2 = 131072;           // bf16 [64][256] swizzled (32768 B)
constexpr int WL_OFF2 = 163840;
constexpr size_t PRE_SMEM_BYTES = 196608; // 192 KB

__device__ __forceinline__ void ldm_x4(uint32_t* r, uint32_t addr) {
    asm volatile("ldmatrix.sync.aligned.m8n8.x4.shared.b16 {%0,%1,%2,%3}, [%4];"
                 : "=r"(r[0]), "=r"(r[1]), "=r"(r[2]), "=r"(r[3]) : "r"(addr));
}
__device__ __forceinline__ void mma_bf16(float* c, const uint32_t* a, const uint32_t* b) {
    asm volatile(
        "mma.sync.aligned.m16n8k16.row.col.f32.bf16.bf16.f32 "
        "{%0,%1,%2,%3}, {%4,%5,%6,%7}, {%8,%9}, {%0,%1,%2,%3};"
        : "+f"(c[0]), "+f"(c[1]), "+f"(c[2]), "+f"(c[3])
        : "r"(a[0]), "r"(a[1]), "r"(a[2]), "r"(a[3]), "r"(b[0]), "r"(b[1]));
}

__global__ void __launch_bounds__(256, 1)
xproj_kernel(const float* __restrict__ Wzx, const float* __restrict__ bz,
             const float* __restrict__ Wrx, const float* __restrict__ br,
             const float* __restrict__ Wcx, const float* __restrict__ bc)
{
    extern __shared__ __align__(16) char smraw[];

    const int tid = threadIdx.x, w = tid >> 5, lane = tid & 31;
    const int nt = blockIdx.x % 12, mg = blockIdx.x / 12;
    const int gate = nt >> 2, j0 = (nt & 3) * 64;
    const int wm = (w >> 1) * 32;
    const int wn = (w & 1) * 32;

    const float* Wsrc = (gate == 0 ? Wzx : (gate == 1 ? Wrx : Wcx)) + (size_t)j0 * HD;
    const float* bsrc = (gate == 0 ? bz : (gate == 1 ? br : bc)) + j0;

    float bias[4][2];
#pragma unroll
    for (int ni = 0; ni < 4; ++ni) {
        int n = wn + ni * 8 + (lane & 3) * 2;
        bias[ni][0] = bsrc[n];
        bias[ni][1] = bsrc[n + 1];
    }

    // convert W tile -> bf16 hi/lo swizzled SMEM
    for (int i = tid; i < 64 * 32; i += 256) {
        int row = i >> 5, c = i & 31;
        float4 f0 = *(const float4*)(Wsrc + row * 256 + c * 8);
        float4 f1 = *(const float4*)(Wsrc + row * 256 + c * 8 + 4);
        float v[8] = {f0.x, f0.y, f0.z, f0.w, f1.x, f1.y, f1.z, f1.w};
        uint32_t h[4], l[4];
#pragma unroll
        for (int q = 0; q < 4; ++q) {
            float a = v[q * 2], b = v[q * 2 + 1];
            uint32_t hp = bf2(a, b);
            float ah = __uint_as_float(hp << 16);
            float bh = __uint_as_float(hp & 0xffff0000u);
            h[q] = hp;
            l[q] = bf2(a - ah, b - bh);
        }
        int dst = row * 512 + ((c ^ (row & 7)) << 4);
        *(uint4*)(smraw + WH_OFF2 + dst) = make_uint4(h[0], h[1], h[2], h[3]);
        *(uint4*)(smraw + WL_OFF2 + dst) = make_uint4(l[0], l[1], l[2], l[3]);
    }

    const uint32_t xh_b = smem_u32(smraw + XH_OFF);
    const uint32_t xl_b = smem_u32(smraw + XL_OFF);
    const uint32_t wh_b = smem_u32(smraw + WH_OFF2);
    const uint32_t wl_b = smem_u32(smraw + WL_OFF2);

    const int lg = lane >> 3, lr = lane & 7;
    uint32_t a_row[2];
    const uint32_t a_half = (uint32_t)(lg >> 1);
#pragma unroll
    for (int mi = 0; mi < 2; ++mi) a_row[mi] = wm + mi * 16 + lr + (lg & 1) * 8;
    uint32_t b_row[2];
    const uint32_t b_half = (uint32_t)(lg & 1);
#pragma unroll
    for (int p = 0; p < 2; ++p) b_row[p] = wn + p * 16 + (lg >> 1) * 8 + lr;

    for (int it = 0; it < 8; ++it) {
        const int m0 = (mg * 8 + it) * 128;
        __syncthreads();
        // copy prestaged bf16 hi/lo X tile into swizzled SMEM
        for (int i = tid; i < 128 * 32; i += 256) {
            int row = i >> 5, c = i & 31;
            size_t src = (size_t)(m0 + row) * 256 + c * 8;
            int dst = row * 512 + ((c ^ (row & 7)) << 4);
            *(uint4*)(smraw + XH_OFF + dst) = *(const uint4*)(Xh_buf + src);
            *(uint4*)(smraw + XL_OFF + dst) = *(const uint4*)(Xl_buf + src);
        }
        __syncthreads();

        float acc[2][4][4];
#pragma unroll
        for (int mi = 0; mi < 2; ++mi)
#pragma unroll
            for (int ni = 0; ni < 4; ++ni)
#pragma unroll
                for (int q = 0; q < 4; ++q) acc[mi][ni][q] = 0.0f;

#pragma unroll
        for (int ks = 0; ks < 16; ++ks) {
            uint32_t ah[2][4], al[2][4], bh[2][4], bl[2][4];
#pragma unroll
            for (int mi = 0; mi < 2; ++mi) {
                uint32_t ch = (uint32_t)(2 * ks) + a_half;
                uint32_t off = a_row[mi] * 512 + ((ch ^ (a_row[mi] & 7)) << 4);
                ldm_x4(ah[mi], xh_b + off);
                ldm_x4(al[mi], xl_b + off);
            }
#pragma unroll
            for (int p = 0; p < 2; ++p) {
                uint32_t ch = (uint32_t)(2 * ks) + b_half;
                uint32_t off = b_row[p] * 512 + ((ch ^ (b_row[p] & 7)) << 4);
                ldm_x4(bh[p], wh_b + off);
                ldm_x4(bl[p], wl_b + off);
            }
#pragma unroll
            for (int mi = 0; mi < 2; ++mi) {
#pragma unroll
                for (int p = 0; p < 2; ++p) {
                    mma_bf16(acc[mi][p * 2 + 0], ah[mi], bh[p] + 0);
                    mma_bf16(acc[mi][p * 2 + 0], ah[mi], bl[p] + 0);
                    mma_bf16(acc[mi][p * 2 + 0], al[mi], bh[p] + 0);
                    mma_bf16(acc[mi][p * 2 + 1], ah[mi], bh[p] + 2);
                    mma_bf16(acc[mi][p * 2 + 1], ah[mi], bl[p] + 2);
                    mma_bf16(acc[mi][p * 2 + 1], al[mi], bh[p] + 2);
                }
            }
        }

#pragma unroll
        for (int mi = 0; mi < 2; ++mi) {
#pragma unroll
            for (int ni = 0; ni < 4; ++ni) {
                int mrow = m0 + wm + mi * 16 + (lane >> 2);
                int ncol = gate * 256 + j0 + wn + ni * 8 + (lane & 3) * 2;
                float* op = XG_buf + (size_t)mrow * 768 + ncol;
                *(float2*)op = make_float2(acc[mi][ni][0] + bias[ni][0],
                                           acc[mi][ni][1] + bias[ni][1]);
                *(float2*)(op + 8 * 768) = make_float2(acc[mi][ni][2] + bias[ni][0],
                                                       acc[mi][ni][3] + bias[ni][1]);
            }
        }
    }
}

// ============================================================================
// Phase 2: recurrence (R7 structure — verified best). Unchanged.
// ============================================================================
constexpr int R_WC = 0;
constexpr int R_H  = 16384;
constexpr int R_RH = 17424;
constexpr int R_Z  = 18464;
constexpr int R_XG = 18736;
constexpr int REC_FLOATS = R_XG + 1632;
constexpr size_t REC_SMEM_BYTES = REC_FLOATS * sizeof(float);

__global__ void __cluster_dims__(4, 1, 1) __launch_bounds__(512, 1)
gru_rec(const float* __restrict__ h0,
        const float* __restrict__ Wzh, const float* __restrict__ Wrh,
        const float* __restrict__ Wch, float* __restrict__ out)
{
    extern __shared__ float sm[];

    const int tid  = threadIdx.x;
    const int wid  = tid >> 5;
    const int lane = tid & 31;
    const int rank = blockIdx.x & 3;
    const int b0   = (blockIdx.x >> 2) << 2;
    const int j0   = rank << 6;

    const int g1 = wid >> 3;
    const int jb = (wid & 7) * 8;
    const int jl = lane >> 3;
    const int kl = lane & 7;
    const int b2 = lane & 3;
    const int ks = lane >> 2;
    const int jc = wid * 4;

    for (int i = tid; i < 4096; i += 512) {
        int row = i >> 6, q = i & 63;
        *(float4*)(sm + R_WC + row * 256 + swq(q) * 4) =
            *(const float4*)(Wch + (size_t)(j0 + row) * 256 + q * 4);
    }
    for (int i = tid; i < 256; i += 512) {
        int bb = i >> 6, q = i & 63;
        *(float4*)(sm + R_H + bb * 260 + swq(q) * 4) =
            *(const float4*)(h0 + (size_t)(b0 + bb) * 256 + q * 4);
    }
    if (tid < 192) {
        int pb = tid / 48, rem = tid % 48, pg = rem >> 4, pq = rem & 15;
        float4 v = *(const float4*)(XG_buf + ((size_t)(b0 + pb) * S + 0) * 768
                                    + pg * 256 + j0 + pq * 4);
        *(float4*)(sm + R_XG + pb * 204 + pg * 68 + pq * 4) = v;
    }

    ull w1[32];
    {
        const float* wsrc = (g1 == 0 ? Wzh : Wrh)
                          + (size_t)(j0 + jb + jl * 2) * 256 + kl * 32;
#pragma unroll
        for (int jt = 0; jt < 2; ++jt)
#pragma unroll
            for (int c = 0; c < 4; ++c) {
                ulonglong2 v0 = *(const ulonglong2*)(wsrc + jt * 256 + c * 8);
                ulonglong2 v1 = *(const ulonglong2*)(wsrc + jt * 256 + c * 8 + 4);
                w1[jt * 16 + c * 4 + 0] = v0.x;
                w1[jt * 16 + c * 4 + 1] = v0.y;
                w1[jt * 16 + c * 4 + 2] = v1.x;
                w1[jt * 16 + c * 4 + 3] = v1.y;
            }
    }
    __syncthreads();
    clu_arrive(); clu_wait();

    const uint32_t base = smem_u32(sm);
    uint32_t rbase[4];
#pragma unroll
    for (int p = 0; p < 4; ++p) rbase[p] = mapa_rank(base, p);

    const int qr = rank * 16 + ((jb + jl * 2) >> 2);
    const uint32_t offRH = (uint32_t)(R_RH + swq(qr) * 4) * 4u;
    const int qh = rank * 16 + wid;
    const uint32_t offH = (uint32_t)(R_H + swq(qh) * 4) * 4u;

    const float* wp2 = sm + R_WC + jc * 256;
    float* outp = out + (size_t)(b0 + b2) * S * 256 + (j0 + jc);

    const int pb = tid / 48, prem = tid % 48, pg = prem >> 4, pq = prem & 15;
    const float* psrc = XG_buf + (size_t)(b0 + pb) * S * 768 + pg * 256 + j0 + pq * 4;

    for (int t = 0; t < S; ++t) {
        float4 pxv;
        if (tid < 192 && t + 1 < S)
            pxv = *(const float4*)(psrc + (size_t)(t + 1) * 768);

        const float* xgb = sm + R_XG + (t & 1) * 816;

        ull acc[8];
#pragma unroll
        for (int i = 0; i < 8; ++i) acc[i] = 0ull;
#pragma unroll
        for (int c = 0; c < 4; ++c) {
#pragma unroll
            for (int b = 0; b < 4; ++b) {
                const float* hb = sm + R_H + b * 260;
                const int p0 = (kl << 3) | ((2 * c + kl) & 7);
                const int p1 = (kl << 3) | ((2 * c + 1 + kl) & 7);
                ulonglong2 h0v = *(const ulonglong2*)(hb + p0 * 4);
                ulonglong2 h1v = *(const ulonglong2*)(hb + p1 * 4);
#pragma unroll
                for (int jt = 0; jt < 2; ++jt) {
                    ffma2(acc[b * 2 + jt], h0v.x, w1[jt * 16 + c * 4 + 0]);
                    ffma2(acc[b * 2 + jt], h0v.y, w1[jt * 16 + c * 4 + 1]);
                    ffma2(acc[b * 2 + jt], h1v.x, w1[jt * 16 + c * 4 + 2]);
                    ffma2(acc[b * 2 + jt], h1v.y, w1[jt * 16 + c * 4 + 3]);
                }
            }
        }
        float s[8];
#pragma unroll
        for (int o = 0; o < 8; ++o) {
            float2 f = unpk(acc[o]);
            float v = f.x + f.y;
            v += __shfl_xor_sync(0xffffffffu, v, 1);
            v += __shfl_xor_sync(0xffffffffu, v, 2);
            v += __shfl_xor_sync(0xffffffffu, v, 4);
            s[o] = v;
        }
        if (kl == 0) {
            if (g1 == 0) {
#pragma unroll
                for (int b = 0; b < 4; ++b)
#pragma unroll
                    for (int jt = 0; jt < 2; ++jt) {
                        int jloc = jb + jl * 2 + jt;
                        sm[R_Z + b * 68 + jloc] =
                            sigm(s[b * 2 + jt] + xgb[b * 204 + jloc]);
                    }
            } else {
                float rr[8];
#pragma unroll
                for (int b = 0; b < 4; ++b)
#pragma unroll
                    for (int jt = 0; jt < 2; ++jt) {
                        int jloc = jb + jl * 2 + jt;
                        int e = j0 + jloc;
                        float hp = sm[R_H + b * 260 + swq(e >> 2) * 4 + (e & 3)];
                        rr[b * 2 + jt] =
                            sigm(s[b * 2 + jt] + xgb[b * 204 + 68 + jloc]) * hp;
                    }
                float pr[8];
#pragma unroll
                for (int o = 0; o < 8; ++o)
                    pr[o] = __shfl_xor_sync(0x01010101u, rr[o], 8);
                if ((jl & 1) == 0) {
#pragma unroll
                    for (int b = 0; b < 4; ++b) {
                        float4 v = make_float4(rr[b * 2], rr[b * 2 + 1],
                                               pr[b * 2], pr[b * 2 + 1]);
                        uint32_t off = offRH + (uint32_t)b * 1040u;
#pragma unroll
                        for (int p = 0; p < 4; ++p) st_clu_v4(rbase[p] + off, v);
                    }
                }
            }
        }
        if (tid < 192 && t + 1 < S)
            *(float4*)(sm + R_XG + ((t + 1) & 1) * 816 + pb * 204 + pg * 68 + pq * 4) = pxv;
        clu_arrive(); clu_wait();

        const float* Rb = sm + R_RH + b2 * 260;
        ull cacc[4] = {0ull, 0ull, 0ull, 0ull};
#pragma unroll
        for (int i = 0; i < 8; ++i) {
            const int pq2 = ks * 8 + ((i + ks) & 7);
            ulonglong2 rv = *(const ulonglong2*)(Rb + pq2 * 4);
            const float* wp = wp2 + pq2 * 4;
#pragma unroll
            for (int jj = 0; jj < 4; ++jj) {
                ulonglong2 wv = *(const ulonglong2*)(wp + jj * 256);
                ffma2(cacc[jj], rv.x, wv.x);
                ffma2(cacc[jj], rv.y, wv.y);
            }
        }
        float cv[4];
#pragma unroll
        for (int o = 0; o < 4; ++o) {
            float2 f = unpk(cacc[o]);
            float v = f.x + f.y;
            v += __shfl_xor_sync(0xffffffffu, v, 4);
            v += __shfl_xor_sync(0xffffffffu, v, 8);
            v += __shfl_xor_sync(0xffffffffu, v, 16);
            cv[o] = v;
        }
        if (lane < 4) {
            float4 hp = *(const float4*)(sm + R_H + b2 * 260 + swq(qh) * 4);
            float4 zg = *(const float4*)(sm + R_Z + b2 * 68 + jc);
            const float* xc = xgb + b2 * 204 + 136 + jc;
            float4 hn;
            hn.x = fmaf(zg.x, tanh_f(cv[0] + xc[0]) - hp.x, hp.x);
            hn.y = fmaf(zg.y, tanh_f(cv[1] + xc[1]) - hp.y, hp.y);
            hn.z = fmaf(zg.z, tanh_f(cv[2] + xc[2]) - hp.z, hp.z);
            hn.w = fmaf(zg.w, tanh_f(cv[3] + xc[3]) - hp.w, hp.w);
            uint32_t off = offH + (uint32_t)b2 * 1040u;
#pragma unroll
            for (int p = 0; p < 4; ++p) st_clu_v4(rbase[p] + off, hn);
            *(float4*)(outp + (size_t)t * 256) = hn;
        }
        clu_arrive(); clu_wait();
    }
}

extern "C" void kernel_launch(void* const* d_in, const int* in_sizes, int n_in,
                              void* d_out, int out_size) {
    const float* x   = (const float*)d_in[0];
    const float* h0  = (const float*)d_in[1];
    const float* Wzx = (const float*)d_in[2];
    const float* bz  = (const float*)d_in[3];
    const float* Wzh = (const float*)d_in[4];
    const float* Wrx = (const float*)d_in[5];
    const float* br  = (const float*)d_in[6];
    const float* Wrh = (const float*)d_in[7];
    const float* Wcx = (const float*)d_in[8];
    const float* bc  = (const float*)d_in[9];
    const float* Wch = (const float*)d_in[10];
    float* out = (float*)d_out;

    cudaFuncSetAttribute(xproj_kernel, cudaFuncAttributeMaxDynamicSharedMemorySize,
                         (int)PRE_SMEM_BYTES);
    cudaFuncSetAttribute(gru_rec, cudaFuncAttributeMaxDynamicSharedMemorySize,
                         (int)REC_SMEM_BYTES);

    // Phase 0: split x into bf16 hi/lo
    xsplit_kernel<<<(int)((size_t)NB * S * HD / 8 / 256), 256>>>(x);
    // Phase 1: input projections (tensor cores, bf16x3)
    xproj_kernel<<<12 * 128, 256, PRE_SMEM_BYTES>>>(Wzx, bz, Wrx, br, Wcx, bc);
    // Phase 2: sequential recurrence
    gru_rec<<<128, 512, REC_SMEM_BYTES>>>(h0, Wzh, Wrh, Wch, out);
}

// round 14
// speedup vs baseline: 1.3718x; 1.2591x over previous
#include <cuda_runtime.h>
#include <cstdint>

using ull = unsigned long long;

constexpr int S  = 1024;
constexpr int HD = 256;
constexpr int NB = 128;

// Precomputed input projections: XG[b][s][gate*256 + j], gate order z,r,c
__device__ float XG_buf[(size_t)NB * S * 768];

__device__ __forceinline__ void ffma2(ull& d, ull a, ull b) {
    asm("fma.rn.f32x2 %0, %1, %2, %0;" : "+l"(d) : "l"(a), "l"(b));
}
__device__ __forceinline__ float2 unpk(ull a) {
    float2 r; asm("mov.b64 {%0, %1}, %2;" : "=f"(r.x), "=f"(r.y) : "l"(a)); return r;
}
__device__ __forceinline__ uint32_t smem_u32(const void* p) {
    uint32_t a;
    asm("{ .reg .u64 t; cvta.to.shared.u64 t, %1; cvt.u32.u64 %0, t; }" : "=r"(a) : "l"(p));
    return a;
}
__device__ __forceinline__ uint32_t mapa_rank(uint32_t addr, uint32_t rank) {
    uint32_t r; asm("mapa.shared::cluster.u32 %0, %1, %2;" : "=r"(r) : "r"(addr), "r"(rank));
    return r;
}
__device__ __forceinline__ void st_clu_v4(uint32_t addr, float4 v) {
    asm volatile("st.shared::cluster.v4.f32 [%0], {%1,%2,%3,%4};"
                 :: "r"(addr), "f"(v.x), "f"(v.y), "f"(v.z), "f"(v.w) : "memory");
}
__device__ __forceinline__ void clu_arrive() {
    asm volatile("barrier.cluster.arrive.aligned;" ::: "memory");
}
__device__ __forceinline__ void clu_wait() {
    asm volatile("barrier.cluster.wait.aligned;" ::: "memory");
}
__device__ __forceinline__ float sigm(float x) { return 1.0f / (1.0f + __expf(-x)); }
__device__ __forceinline__ float tanh_f(float x) {
    x = fminf(fmaxf(x, -15.0f), 15.0f);
    float e = __expf(-2.0f * x);
    return __fdividef(1.0f - e, 1.0f + e);
}
// quad rotation swizzle: logical quad q -> physical quad (rotate within 8-quad group)
__device__ __forceinline__ int swq(int q) { return (q & ~7) | ((q + (q >> 3)) & 7); }

// ============================================================================
// Phase 1: XG = x @ Wg^T + bias  (proven fp32 FFMA2 version, ~1.37 ms)
// ============================================================================
constexpr int PRE_SMEM_FLOATS = 32768 + 64 * 260;
constexpr size_t PRE_SMEM_BYTES = PRE_SMEM_FLOATS * sizeof(float);

__global__ void __launch_bounds__(256, 1)
xproj_kernel(const float* __restrict__ x,
             const float* __restrict__ Wzx, const float* __restrict__ bz,
             const float* __restrict__ Wrx, const float* __restrict__ br,
             const float* __restrict__ Wcx, const float* __restrict__ bc)
{
    extern __shared__ float smp[];
    float* XS = smp;            // [128][256]
    float* WS = smp + 32768;    // [64][260]

    const int tid = threadIdx.x, w = tid >> 5, lane = tid & 31;
    const int nt = blockIdx.x % 12, mg = blockIdx.x / 12;
    const int gate = nt >> 2, j0 = (nt & 3) * 64;

    const float* Wsrc = (gate == 0 ? Wzx : (gate == 1 ? Wrx : Wcx)) + (size_t)j0 * HD;
    const float* bsrc = (gate == 0 ? bz : (gate == 1 ? br : bc)) + j0;
    const float b0v = bsrc[lane];
    const float b1v = bsrc[lane + 32];

    for (int i = tid; i < 64 * 64; i += 256) {
        int row = i >> 6, q = i & 63;
        *(float4*)(WS + row * 260 + q * 4) = *(const float4*)(Wsrc + row * 256 + q * 4);
    }

    const int r0 = w * 16;
    for (int it = 0; it < 8; ++it) {
        const int m = mg * 8 + it;
        __syncthreads();
        const float* xs = x + (size_t)m * 128 * HD;
#pragma unroll 8
        for (int i = tid; i < 8192; i += 256)
            *(float4*)(XS + i * 4) = *(const float4*)(xs + (size_t)i * 4);
        __syncthreads();

        ull acc[32];
#pragma unroll
        for (int i = 0; i < 32; ++i) acc[i] = 0ull;

#pragma unroll 4
        for (int kq = 0; kq < 64; ++kq) {
            ulonglong2 wv0 = *(const ulonglong2*)(WS + lane * 260 + kq * 4);
            ulonglong2 wv1 = *(const ulonglong2*)(WS + (lane + 32) * 260 + kq * 4);
#pragma unroll
            for (int r = 0; r < 16; ++r) {
                ulonglong2 xv = *(const ulonglong2*)(XS + (r0 + r) * 256 + kq * 4);
                ffma2(acc[r * 2 + 0], xv.x, wv0.x);
                ffma2(acc[r * 2 + 0], xv.y, wv0.y);
                ffma2(acc[r * 2 + 1], xv.x, wv1.x);
                ffma2(acc[r * 2 + 1], xv.y, wv1.y);
            }
        }

        float* op = XG_buf + ((size_t)m * 128 + r0) * 768 + gate * 256 + j0;
#pragma unroll
        for (int r = 0; r < 16; ++r) {
            float2 f0 = unpk(acc[r * 2 + 0]);
            float2 f1 = unpk(acc[r * 2 + 1]);
            op[(size_t)r * 768 + lane]      = f0.x + f0.y + b0v;
            op[(size_t)r * 768 + lane + 32] = f1.x + f1.y + b1v;
        }
    }
}

// ============================================================================
// Phase 2: recurrence. 32 clusters x 8 CTAs x 256 threads (2 CTAs/SM —
// two independent barrier domains per SM to overlap sync stalls).
// CTA owns a 32-j slice. Phase1 (z+r): W in regs (2j x 32k per thread).
// Phase2 (c): Wc in SMEM, warp = 4 j, lane = b(4) x ks(8).
// ============================================================================
constexpr int R_WC = 0;                    // [32][256] c-gate weights, quad-swizzled
constexpr int R_H  = 8192;                 // [4][260]  h, quad-swizzled rows
constexpr int R_RH = 9232;                 // [4][260]  r*h, quad-swizzled rows
constexpr int R_Z  = 10272;                // [4][36]
constexpr int R_XG = 10416;                // [2][4][3][36] = 864 floats
constexpr int REC_FLOATS = R_XG + 864;     // 11280
constexpr size_t REC_SMEM_BYTES = REC_FLOATS * sizeof(float);  // 45120 B

__global__ void __cluster_dims__(8, 1, 1) __launch_bounds__(256, 2)
gru_rec(const float* __restrict__ h0,
        const float* __restrict__ Wzh, const float* __restrict__ Wrh,
        const float* __restrict__ Wch, float* __restrict__ out)
{
    extern __shared__ float sm[];

    const int tid  = threadIdx.x;
    const int wid  = tid >> 5;         // 0..7
    const int lane = tid & 31;
    const int rank = blockIdx.x & 7;
    const int b0   = (blockIdx.x >> 3) << 2;   // 4 batch rows per cluster
    const int j0   = rank << 5;                // 32-j slice

    // phase-1 identity: gate (z: warps 0-3, r: warps 4-7), 8 j per warp
    const int g1 = wid >> 2;
    const int jb = (wid & 3) * 8;
    const int jl = lane >> 3;          // j-lane 0..3 (2 j each)
    const int kl = lane & 7;           // k-lane 0..7 (32 k each)
    // phase-2 identity: lane = b(4) x ks(8), warp = 4 j
    const int b2 = lane & 3;
    const int ks = lane >> 2;
    const int jc = wid * 4;

    // ---- init SMEM: Wc (quad-swizzled), h0 (quad-swizzled) ----
    for (int i = tid; i < 2048; i += 256) {
        int row = i >> 6, q = i & 63;
        *(float4*)(sm + R_WC + row * 256 + swq(q) * 4) =
            *(const float4*)(Wch + (size_t)(j0 + row) * 256 + q * 4);
    }
    for (int i = tid; i < 256; i += 256) {
        int bb = i >> 6, q = i & 63;
        *(float4*)(sm + R_H + bb * 260 + swq(q) * 4) =
            *(const float4*)(h0 + (size_t)(b0 + bb) * 256 + q * 4);
    }
    // preload XG for t=0 into buffer 0 (96 float4)
    if (tid < 96) {
        int pb = tid / 24, rem = tid % 24, pg = rem >> 3, pq = rem & 7;
        float4 v = *(const float4*)(XG_buf + ((size_t)(b0 + pb) * S + 0) * 768
                                    + pg * 256 + j0 + pq * 4);
        *(float4*)(sm + R_XG + pb * 108 + pg * 36 + pq * 4) = v;
    }

    // ---- phase-1 weights -> registers (2 j x 32 k per thread) ----
    ull w1[32];
    {
        const float* wsrc = (g1 == 0 ? Wzh : Wrh)
                          + (size_t)(j0 + jb + jl * 2) * 256 + kl * 32;
#pragma unroll
        for (int jt = 0; jt < 2; ++jt)
#pragma unroll
            for (int c = 0; c < 4; ++c) {
                ulonglong2 v0 = *(const ulonglong2*)(wsrc + jt * 256 + c * 8);
                ulonglong2 v1 = *(const ulonglong2*)(wsrc + jt * 256 + c * 8 + 4);
                w1[jt * 16 + c * 4 + 0] = v0.x;
                w1[jt * 16 + c * 4 + 1] = v0.y;
                w1[jt * 16 + c * 4 + 2] = v1.x;
                w1[jt * 16 + c * 4 + 3] = v1.y;
            }
    }
    __syncthreads();
    clu_arrive(); clu_wait();

    const uint32_t base = smem_u32(sm);
    uint32_t rbase[8];
#pragma unroll
    for (int p = 0; p < 8; ++p) rbase[p] = mapa_rank(base, p);

    const int qr = rank * 8 + ((jb + jl * 2) >> 2);
    const uint32_t offRH = (uint32_t)(R_RH + swq(qr) * 4) * 4u;
    const int qh = rank * 8 + wid;
    const uint32_t offH = (uint32_t)(R_H + swq(qh) * 4) * 4u;

    const float* wp2 = sm + R_WC + jc * 256;
    float* outp = out + (size_t)(b0 + b2) * S * 256 + (j0 + jc);

    const int pb = tid / 24, prem = tid % 24, pg = prem >> 3, pq = prem & 7;
    const float* psrc = XG_buf + (size_t)(b0 + pb) * S * 768 + pg * 256 + j0 + pq * 4;

    for (int t = 0; t < S; ++t) {
        // prefetch next step's XG (global -> regs)
        float4 pxv;
        if (tid < 96 && t + 1 < S)
            pxv = *(const float4*)(psrc + (size_t)(t + 1) * 768);

        const float* xgb = sm + R_XG + (t & 1) * 432;

        // ================= phase 1: z / r gates (register W) =================
        ull acc[8];
#pragma unroll
        for (int i = 0; i < 8; ++i) acc[i] = 0ull;
#pragma unroll
        for (int c = 0; c < 4; ++c) {
#pragma unroll
            for (int b = 0; b < 4; ++b) {
                const float* hb = sm + R_H + b * 260;
                const int p0 = (kl << 3) | ((2 * c + kl) & 7);
                const int p1 = (kl << 3) | ((2 * c + 1 + kl) & 7);
                ulonglong2 h0v = *(const ulonglong2*)(hb + p0 * 4);
                ulonglong2 h1v = *(const ulonglong2*)(hb + p1 * 4);
#pragma unroll
                for (int jt = 0; jt < 2; ++jt) {
                    ffma2(acc[b * 2 + jt], h0v.x, w1[jt * 16 + c * 4 + 0]);
                    ffma2(acc[b * 2 + jt], h0v.y, w1[jt * 16 + c * 4 + 1]);
                    ffma2(acc[b * 2 + jt], h1v.x, w1[jt * 16 + c * 4 + 2]);
                    ffma2(acc[b * 2 + jt], h1v.y, w1[jt * 16 + c * 4 + 3]);
                }
            }
        }
        float s[8];
#pragma unroll
        for (int o = 0; o < 8; ++o) {
            float2 f = unpk(acc[o]);
            float v = f.x + f.y;
            v += __shfl_xor_sync(0xffffffffu, v, 1);
            v += __shfl_xor_sync(0xffffffffu, v, 2);
            v += __shfl_xor_sync(0xffffffffu, v, 4);
            s[o] = v;
        }
        if (kl == 0) {
            if (g1 == 0) {
                // z gate -> local SMEM
#pragma unroll
                for (int b = 0; b < 4; ++b)
#pragma unroll
                    for (int jt = 0; jt < 2; ++jt) {
                        int jloc = jb + jl * 2 + jt;
                        sm[R_Z + b * 36 + jloc] =
                            sigm(s[b * 2 + jt] + xgb[b * 108 + jloc]);
                    }
            } else {
                // r gate: rr = sigm * hprev, pack j-quad via partner shfl, push
                float rr[8];
#pragma unroll
                for (int b = 0; b < 4; ++b)
#pragma unroll
                    for (int jt = 0; jt < 2; ++jt) {
                        int jloc = jb + jl * 2 + jt;
                        int e = j0 + jloc;
                        float hp = sm[R_H + b * 260 + swq(e >> 2) * 4 + (e & 3)];
                        rr[b * 2 + jt] =
                            sigm(s[b * 2 + jt] + xgb[b * 108 + 36 + jloc]) * hp;
                    }
                float pr[8];
#pragma unroll
                for (int o = 0; o < 8; ++o)
                    pr[o] = __shfl_xor_sync(0x01010101u, rr[o], 8);
                if ((jl & 1) == 0) {
#pragma unroll
                    for (int b = 0; b < 4; ++b) {
                        float4 v = make_float4(rr[b * 2], rr[b * 2 + 1],
                                               pr[b * 2], pr[b * 2 + 1]);
                        uint32_t off = offRH + (uint32_t)b * 1040u;
#pragma unroll
                        for (int p = 0; p < 8; ++p) st_clu_v4(rbase[p] + off, v);
                    }
                }
            }
        }
        // commit next-step XG while cluster drains
        if (tid < 96 && t + 1 < S)
            *(float4*)(sm + R_XG + ((t + 1) & 1) * 432 + pb * 108 + pg * 36 + pq * 4) = pxv;
        clu_arrive(); clu_wait();

        // ================= phase 2: candidate gate (SMEM W) =================
        const float* Rb = sm + R_RH + b2 * 260;
        ull cacc[4] = {0ull, 0ull, 0ull, 0ull};
#pragma unroll
        for (int i = 0; i < 8; ++i) {
            const int pq2 = ks * 8 + ((i + ks) & 7);
            ulonglong2 rv = *(const ulonglong2*)(Rb + pq2 * 4);
            const float* wp = wp2 + pq2 * 4;
#pragma unroll
            for (int jj = 0; jj < 4; ++jj) {
                ulonglong2 wv = *(const ulonglong2*)(wp + jj * 256);
                ffma2(cacc[jj], rv.x, wv.x);
                ffma2(cacc[jj], rv.y, wv.y);
            }
        }
        float cv[4];
#pragma unroll
        for (int o = 0; o < 4; ++o) {
            float2 f = unpk(cacc[o]);
            float v = f.x + f.y;
            v += __shfl_xor_sync(0xffffffffu, v, 4);
            v += __shfl_xor_sync(0xffffffffu, v, 8);
            v += __shfl_xor_sync(0xffffffffu, v, 16);
            cv[o] = v;
        }
        if (lane < 4) {
            float4 hp = *(const float4*)(sm + R_H + b2 * 260 + swq(qh) * 4);
            float4 zg = *(const float4*)(sm + R_Z + b2 * 36 + jc);
            const float* xc = xgb + b2 * 108 + 72 + jc;
            float4 hn;
            hn.x = fmaf(zg.x, tanh_f(cv[0] + xc[0]) - hp.x, hp.x);
            hn.y = fmaf(zg.y, tanh_f(cv[1] + xc[1]) - hp.y, hp.y);
            hn.z = fmaf(zg.z, tanh_f(cv[2] + xc[2]) - hp.z, hp.z);
            hn.w = fmaf(zg.w, tanh_f(cv[3] + xc[3]) - hp.w, hp.w);
            uint32_t off = offH + (uint32_t)b2 * 1040u;
#pragma unroll
            for (int p = 0; p < 8; ++p) st_clu_v4(rbase[p] + off, hn);
            *(float4*)(outp + (size_t)t * 256) = hn;
        }
        clu_arrive(); clu_wait();
    }
}

extern "C" void kernel_launch(void* const* d_in, const int* in_sizes, int n_in,
                              void* d_out, int out_size) {
    const float* x   = (const float*)d_in[0];
    const float* h0  = (const float*)d_in[1];
    const float* Wzx = (const float*)d_in[2];
    const float* bz  = (const float*)d_in[3];
    const float* Wzh = (const float*)d_in[4];
    const float* Wrx = (const float*)d_in[5];
    const float* br  = (const float*)d_in[6];
    const float* Wrh = (const float*)d_in[7];
    const float* Wcx = (const float*)d_in[8];
    const float* bc  = (const float*)d_in[9];
    const float* Wch = (const float*)d_in[10];
    float* out = (float*)d_out;

    cudaFuncSetAttribute(xproj_kernel, cudaFuncAttributeMaxDynamicSharedMemorySize,
                         (int)PRE_SMEM_BYTES);
    cudaFuncSetAttribute(gru_rec, cudaFuncAttributeMaxDynamicSharedMemorySize,
                         (int)REC_SMEM_BYTES);

    // Phase 1: input projections (fp32 FFMA2, proven)
    xproj_kernel<<<12 * 128, 256, PRE_SMEM_BYTES>>>(x, Wzx, bz, Wrx, br, Wcx, bc);
    // Phase 2: recurrence — 32 clusters x 8 CTAs x 256 threads (2 CTAs/SM)
    gru_rec<<<256, 256, REC_SMEM_BYTES>>>(h0, Wzh, Wrh, Wch, out);
}